// round 3
// baseline (speedup 1.0000x reference)
#include <cuda_runtime.h>

#define NN 100000
#define EE 1600000

typedef unsigned long long ull;

// Scratch (allocation-free rule: __device__ globals)
__device__ float g_kw [NN * 128];   // interleaved: [n][0:64]=k row, [n][64:128]=hw row
__device__ float g_q  [NN * 64];
__device__ int   g_cnt [NN];
__device__ int   g_roff[NN + 1];
__device__ int   g_cur [NN];
__device__ int   g_bsum[512];
__device__ int   g_boff[512];
__device__ int   g_esrc[EE];

// ---- packed f32x2 helpers (sm_103a dual-FMA pipe) -------------------------
__device__ __forceinline__ ull pk2(float x, float y)
{
    ull r; asm("mov.b64 %0, {%1,%2};" : "=l"(r) : "f"(x), "f"(y)); return r;
}
__device__ __forceinline__ ull f2fma(ull a, ull b, ull c)
{
    ull d; asm("fma.rn.f32x2 %0, %1, %2, %3;" : "=l"(d) : "l"(a), "l"(b), "l"(c));
    return d;
}
__device__ __forceinline__ float2 upk2(ull v)
{
    float2 f; asm("mov.b64 {%0,%1}, %2;" : "=f"(f.x), "=f"(f.y) : "l"(v)); return f;
}

// ---------------------------------------------------------------------------
// Kernel 1: k = h@Wk, q = h@Wq, hw = h@W  (three 64x64 projections, fused)
// Node-pair accumulation in packed f32x2 registers. h tile transposed in smem
// so a node-pair load is one warp-uniform LDS.64.
// ---------------------------------------------------------------------------
__global__ __launch_bounds__(256) void gemm3_kernel(
    const float* __restrict__ h,
    const float* __restrict__ Wk,
    const float* __restrict__ Wq,
    const float* __restrict__ Ww,
    int N)
{
    __shared__ float sWk[64 * 68];
    __shared__ float sWq[64 * 68];
    __shared__ float sWw[64 * 68];
    __shared__ __align__(16) float shT[64 * 34];   // shT[i*34 + n] = h[base+n][i]

    const int tid = threadIdx.x;

    // Weights transposed: sW[col*68 + i] = W[i*64 + col]
    for (int idx = tid; idx < 64 * 64; idx += 256) {
        int i = idx >> 6, c = idx & 63;
        sWk[c * 68 + i] = Wk[idx];
        sWq[c * 68 + i] = Wq[idx];
        sWw[c * 68 + i] = Ww[idx];
    }
    const int base = blockIdx.x * 32;
    for (int idx = tid; idx < 32 * 64; idx += 256) {
        int n = idx >> 6, c = idx & 63;
        int gn = base + n;
        shT[c * 34 + n] = (gn < N) ? h[(size_t)gn * 64 + c] : 0.f;
    }
    __syncthreads();

    const int col = tid & 63;
    const int grp = tid >> 6;    // 4 groups x 8 nodes (4 node-pairs per thread)

    ull ak[4], aq[4], aw[4];
#pragma unroll
    for (int p = 0; p < 4; p++) { ak[p] = 0ull; aq[p] = 0ull; aw[p] = 0ull; }

    const float4* wk4 = (const float4*)(sWk + col * 68);
    const float4* wq4 = (const float4*)(sWq + col * 68);
    const float4* ww4 = (const float4*)(sWw + col * 68);

#pragma unroll
    for (int i4 = 0; i4 < 16; i4++) {
        const float4 wk = wk4[i4];
        const float4 wq = wq4[i4];
        const float4 ww = ww4[i4];
#pragma unroll
        for (int j = 0; j < 4; j++) {
            const int kk = i4 * 4 + j;
            const float wkj = (&wk.x)[j];
            const float wqj = (&wq.x)[j];
            const float wwj = (&ww.x)[j];
            const ull wk2 = pk2(wkj, wkj);
            const ull wq2 = pk2(wqj, wqj);
            const ull ww2 = pk2(wwj, wwj);
            const float* hp = shT + kk * 34 + grp * 8;
#pragma unroll
            for (int p = 0; p < 4; p++) {
                const ull h2 = *(const ull*)(hp + 2 * p);   // {h[n0][kk], h[n1][kk]}
                ak[p] = f2fma(h2, wk2, ak[p]);
                aq[p] = f2fma(h2, wq2, aq[p]);
                aw[p] = f2fma(h2, ww2, aw[p]);
            }
        }
    }

#pragma unroll
    for (int p = 0; p < 4; p++) {
        const float2 rk = upk2(ak[p]);
        const float2 rq = upk2(aq[p]);
        const float2 rw = upk2(aw[p]);
        const int gn = base + grp * 8 + 2 * p;
        if (gn < N) {
            g_kw[(size_t)gn * 128 + col]      = rk.x;
            g_kw[(size_t)gn * 128 + 64 + col] = rw.x;
            g_q [(size_t)gn * 64 + col]       = rq.x;
        }
        if (gn + 1 < N) {
            g_kw[(size_t)(gn + 1) * 128 + col]      = rk.y;
            g_kw[(size_t)(gn + 1) * 128 + 64 + col] = rw.y;
            g_q [(size_t)(gn + 1) * 64 + col]       = rq.y;
        }
    }
}

// ---------------------------------------------------------------------------
// CSR construction: zero counts -> histogram -> 3-kernel exclusive scan -> scatter
// ---------------------------------------------------------------------------
__global__ void zero_cnt_kernel(int N)
{
    int i = blockIdx.x * blockDim.x + threadIdx.x;
    if (i < N) g_cnt[i] = 0;
}

__global__ void hist_kernel(const int* __restrict__ dst, int E)
{
    int i = blockIdx.x * blockDim.x + threadIdx.x;
    if (i < E) atomicAdd(&g_cnt[dst[i]], 1);
}

__global__ __launch_bounds__(256) void scan1_kernel(int N)
{
    __shared__ int s[256];
    const int t = threadIdx.x;
    const int i = blockIdx.x * 256 + t;
    int v = (i < N) ? g_cnt[i] : 0;
    s[t] = v;
    __syncthreads();
#pragma unroll
    for (int off = 1; off < 256; off <<= 1) {
        int x = (t >= off) ? s[t - off] : 0;
        __syncthreads();
        if (t >= off) s[t] += x;
        __syncthreads();
    }
    if (i < N) g_roff[i] = s[t] - v;     // exclusive within block
    if (t == 255) g_bsum[blockIdx.x] = s[255];
}

__global__ __launch_bounds__(512) void scan2_kernel(int nb)
{
    __shared__ int s[512];
    const int t = threadIdx.x;
    int v = (t < nb) ? g_bsum[t] : 0;
    s[t] = v;
    __syncthreads();
#pragma unroll
    for (int off = 1; off < 512; off <<= 1) {
        int x = (t >= off) ? s[t - off] : 0;
        __syncthreads();
        if (t >= off) s[t] += x;
        __syncthreads();
    }
    if (t < nb) g_boff[t] = s[t] - v;    // exclusive block offsets
}

__global__ void scan3_kernel(int N, int E)
{
    int i = blockIdx.x * blockDim.x + threadIdx.x;
    if (i < N) {
        int r = g_roff[i] + g_boff[i >> 8];
        g_roff[i] = r;
        g_cur[i]  = r;
    }
    if (i == 0) g_roff[N] = E;
}

__global__ void scatter_kernel(const int* __restrict__ src,
                               const int* __restrict__ dst, int E)
{
    int i = blockIdx.x * blockDim.x + threadIdx.x;
    if (i < E) {
        int p = atomicAdd(&g_cur[dst[i]], 1);
        g_esrc[p] = src[i];
    }
}

// ---------------------------------------------------------------------------
// Fused edge-softmax + aggregation. One warp per destination node.
// Lane = head(2b) * 8 + feature-chunk(3b). After the 3-step xor reduce, every
// lane of an 8-lane group holds its head's dot -> no broadcast shuffles, and z
// accumulates redundantly per lane. Register accumulation, single output write
// with bias + 1/z folded in. No atomics.
// ---------------------------------------------------------------------------
__global__ __launch_bounds__(256) void gather_kernel(
    const float* __restrict__ b,
    float* __restrict__ out,
    int N)
{
    const int n    = (blockIdx.x * 256 + threadIdx.x) >> 5;
    const int lane = threadIdx.x & 31;
    if (n >= N) return;
    const int hh = lane >> 3;   // head
    const int cc = lane & 7;    // 8-feature chunk within head

    const float2 q2 = ((const float2*)(g_q + (size_t)n * 64))[lane];
    const int p0 = g_roff[n];
    const int p1 = g_roff[n + 1];

    float4 accA = make_float4(0.f, 0.f, 0.f, 0.f), accB = accA;
    float z = 0.f;

    if (p0 < p1) {
        int s = g_esrc[p0];
        const float* row = g_kw + (size_t)s * 128;
        float2 k2 = ((const float2*)row)[lane];
        float4 hA = ((const float4*)(row + 64))[cc * 2];
        float4 hB = ((const float4*)(row + 64))[cc * 2 + 1];

        for (int p = p0; p < p1; p++) {
            const float2 k2c = k2;
            const float4 hAc = hA, hBc = hB;
            if (p + 1 < p1) {
                int sn = g_esrc[p + 1];
                const float* rn = g_kw + (size_t)sn * 128;
                k2 = ((const float2*)rn)[lane];
                hA = ((const float4*)(rn + 64))[cc * 2];
                hB = ((const float4*)(rn + 64))[cc * 2 + 1];
            }

            float prod = k2c.x * q2.x + k2c.y * q2.y;
            prod += __shfl_xor_sync(0xffffffffu, prod, 4);
            prod += __shfl_xor_sync(0xffffffffu, prod, 2);
            prod += __shfl_xor_sync(0xffffffffu, prod, 1);
            const float e = __expf(prod);      // per-head value, in all 8 lanes

            z += e;
            accA.x += e * hAc.x; accA.y += e * hAc.y;
            accA.z += e * hAc.z; accA.w += e * hAc.w;
            accB.x += e * hBc.x; accB.y += e * hBc.y;
            accB.z += e * hBc.z; accB.w += e * hBc.w;
        }
    }

    const float inv = (z > 0.f) ? 1.f / z : 0.f;
    const float4 b0 = ((const float4*)b)[cc * 2];
    const float4 b1 = ((const float4*)b)[cc * 2 + 1];

    float* op = out + (size_t)n * 256 + hh * 64 + cc * 8;
    ((float4*)op)[0] = make_float4(accA.x * inv + b0.x, accA.y * inv + b0.y,
                                   accA.z * inv + b0.z, accA.w * inv + b0.w);
    ((float4*)op)[1] = make_float4(accB.x * inv + b1.x, accB.y * inv + b1.y,
                                   accB.z * inv + b1.z, accB.w * inv + b1.w);
}

// ---------------------------------------------------------------------------
extern "C" void kernel_launch(void* const* d_in, const int* in_sizes, int n_in,
                              void* d_out, int out_size)
{
    const float* h   = (const float*)d_in[0];
    const int*   src = (const int*)  d_in[1];
    const int*   dst = (const int*)  d_in[2];
    const float* Wk  = (const float*)d_in[3];
    const float* Wq  = (const float*)d_in[4];
    const float* Ww  = (const float*)d_in[5];
    const float* b   = (const float*)d_in[6];
    float*       out = (float*)d_out;

    const int N  = in_sizes[0] / 64;
    const int E  = in_sizes[1];
    const int nb = (N + 255) / 256;

    // Created once on the (uncaptured) correctness call; reused inside capture.
    static cudaStream_t sideStream = nullptr;
    static cudaEvent_t  evFork = nullptr, evJoin = nullptr;
    if (sideStream == nullptr) {
        cudaStreamCreateWithFlags(&sideStream, cudaStreamNonBlocking);
        cudaEventCreateWithFlags(&evFork, cudaEventDisableTiming);
        cudaEventCreateWithFlags(&evJoin, cudaEventDisableTiming);
    }

    // Fork: gemm3 (h,W only) runs concurrently with the CSR build (src,dst only).
    cudaEventRecord(evFork, 0);
    cudaStreamWaitEvent(sideStream, evFork, 0);
    gemm3_kernel<<<(N + 31) / 32, 256, 0, sideStream>>>(h, Wk, Wq, Ww, N);
    cudaEventRecord(evJoin, sideStream);

    zero_cnt_kernel<<<(N + 255) / 256, 256>>>(N);
    hist_kernel<<<(E + 255) / 256, 256>>>(dst, E);
    scan1_kernel<<<nb, 256>>>(N);
    scan2_kernel<<<1, 512>>>(nb);
    scan3_kernel<<<(N + 255) / 256, 256>>>(N, E);
    scatter_kernel<<<(E + 255) / 256, 256>>>(src, dst, E);

    // Join, then the gather needs both gemm outputs and the CSR.
    cudaStreamWaitEvent(0, evJoin, 0);
    gather_kernel<<<(N + 7) / 8, 256>>>(b, out, N);
}